// round 11
// baseline (speedup 1.0000x reference)
#include <cuda_runtime.h>
#include <cuda_bf16.h>
#include <cstdint>
#include <math.h>

#define TOKS 2048
#define HID  768
#define NEXP 128
#define FI   1856
#define FS   3712
#define NTOP 6
#define ECAP 192
#define RSCALE 2.5f

// ---------------- scratch (device globals; no allocation) ----------------
__device__ float g_logits[TOKS * NEXP];
__device__ int   g_counts[NEXP];
__device__ int   g_slot_tok[NEXP * ECAP];
__device__ float g_slot_w[NEXP * ECAP];
__device__ float g_inter_r[(size_t)NEXP * ECAP * FI];   // ~182 MB
__device__ float g_inter_s[(size_t)TOKS * FS];          // ~30 MB

// ---------------- smem geometry ----------------
#define A_STRIDE 36
#define B_STRIDE 136
#define A_BUFSZ  (128 * A_STRIDE)
#define B_BASEF  (2 * A_BUFSZ)
#define B_BUFSZ  (32 * B_STRIDE)
#define SMEM_BYTES ((2 * A_BUFSZ + 2 * B_BUFSZ) * 4)

// ---------------- PTX helpers ----------------
__device__ __forceinline__ uint32_t f2tf32(float f) {
    uint32_t u; asm("cvt.rna.tf32.f32 %0, %1;" : "=r"(u) : "f"(f)); return u;
}
__device__ __forceinline__ void mma_tf32(float* c, const uint32_t* a, uint32_t b0, uint32_t b1) {
    asm volatile("mma.sync.aligned.m16n8k8.row.col.f32.tf32.tf32.f32 "
        "{%0,%1,%2,%3},{%4,%5,%6,%7},{%8,%9},{%0,%1,%2,%3};"
        : "+f"(c[0]), "+f"(c[1]), "+f"(c[2]), "+f"(c[3])
        : "r"(a[0]), "r"(a[1]), "r"(a[2]), "r"(a[3]), "r"(b0), "r"(b1));
}
__device__ __forceinline__ void cp16(uint32_t dst, const float* src, bool valid) {
    int sz = valid ? 16 : 0;
    asm volatile("cp.async.cg.shared.global [%0], [%1], 16, %2;\n" :: "r"(dst), "l"(src), "r"(sz));
}
__device__ __forceinline__ void cp_commit() { asm volatile("cp.async.commit_group;\n"); }
template<int N> __device__ __forceinline__ void cp_wait() {
    asm volatile("cp.async.wait_group %0;\n" :: "n"(N));
}

// ---------------- k0: zero counters ----------------
__global__ void k_zero_counts() { if (threadIdx.x < NEXP) g_counts[threadIdx.x] = 0; }

// ---------------- k1: router logits (fp32, exact) ----------------
__global__ __launch_bounds__(256) void k_logits(const float* __restrict__ X,
                                                const float* __restrict__ Wg) {
    __shared__ float xs[64][16];
    __shared__ float ws[16][132];
    const int tid = threadIdx.x, t0 = blockIdx.x * 64;
    const int tt = tid >> 5, ee = tid & 31;
    float acc[8][4];
#pragma unroll
    for (int i = 0; i < 8; i++) { acc[i][0]=acc[i][1]=acc[i][2]=acc[i][3]=0.f; }
    for (int k0 = 0; k0 < HID; k0 += 16) {
#pragma unroll
        for (int i = 0; i < 4; i++) {
            int idx = tid + 256 * i;
            xs[idx >> 4][idx & 15] = X[(size_t)(t0 + (idx >> 4)) * HID + k0 + (idx & 15)];
        }
#pragma unroll
        for (int i = 0; i < 8; i++) {
            int idx = tid + 256 * i, e = idx >> 4, k = idx & 15;
            ws[k][e] = Wg[(size_t)e * HID + k0 + k];
        }
        __syncthreads();
#pragma unroll
        for (int k = 0; k < 16; k++) {
            float4 w4 = *reinterpret_cast<const float4*>(&ws[k][ee * 4]);
#pragma unroll
            for (int i = 0; i < 8; i++) {
                float xv = xs[tt * 8 + i][k];
                acc[i][0] += xv * w4.x; acc[i][1] += xv * w4.y;
                acc[i][2] += xv * w4.z; acc[i][3] += xv * w4.w;
            }
        }
        __syncthreads();
    }
#pragma unroll
    for (int i = 0; i < 8; i++)
#pragma unroll
        for (int j = 0; j < 4; j++)
            g_logits[(size_t)(t0 + tt * 8 + i) * NEXP + ee * 4 + j] = acc[i][j];
}

// ---------------- k2: top-6 + capacity dispatch (warp per token) ----------------
__global__ __launch_bounds__(256) void k_topk(const float* __restrict__ e_bias) {
    const int warp = threadIdx.x >> 5, lane = threadIdx.x & 31;
    const int t = blockIdx.x * 8 + warp;
    float4 lg4 = *reinterpret_cast<const float4*>(&g_logits[(size_t)t * NEXP + lane * 4]);
    float4 b4  = *reinterpret_cast<const float4*>(&e_bias[lane * 4]);
    float sig[4], ch[4];
    sig[0] = 1.f / (1.f + expf(-lg4.x)); ch[0] = sig[0] + b4.x;
    sig[1] = 1.f / (1.f + expf(-lg4.y)); ch[1] = sig[1] + b4.y;
    sig[2] = 1.f / (1.f + expf(-lg4.z)); ch[2] = sig[2] + b4.z;
    sig[3] = 1.f / (1.f + expf(-lg4.w)); ch[3] = sig[3] + b4.w;

    int my_ex = 0; float my_sig = 0.f;
    float wsum = 0.f;
#pragma unroll
    for (int r = 0; r < NTOP; r++) {
        float bv = ch[0]; int bi = lane * 4;
        if (ch[1] > bv) { bv = ch[1]; bi = lane * 4 + 1; }
        if (ch[2] > bv) { bv = ch[2]; bi = lane * 4 + 2; }
        if (ch[3] > bv) { bv = ch[3]; bi = lane * 4 + 3; }
#pragma unroll
        for (int s = 16; s > 0; s >>= 1) {
            float ov = __shfl_xor_sync(0xffffffffu, bv, s);
            int   oi = __shfl_xor_sync(0xffffffffu, bi, s);
            if (ov > bv || (ov == bv && oi < bi)) { bv = ov; bi = oi; }
        }
        int j = bi & 3;
        float sj = (j == 0) ? sig[0] : (j == 1) ? sig[1] : (j == 2) ? sig[2] : sig[3];
        float ws = __shfl_sync(0xffffffffu, sj, bi >> 2);
        wsum += ws;
        if (lane == r) { my_ex = bi; my_sig = ws; }
        if (lane == (bi >> 2)) {
            if (j == 0) ch[0] = -1e30f; else if (j == 1) ch[1] = -1e30f;
            else if (j == 2) ch[2] = -1e30f; else ch[3] = -1e30f;
        }
    }
    if (lane < NTOP) {
        float w = my_sig / (wsum + 1e-20f) * RSCALE;
        int pos = atomicAdd(&g_counts[my_ex], 1);
        if (pos < ECAP) {
            g_slot_tok[my_ex * ECAP + pos] = t;
            g_slot_w[my_ex * ECAP + pos] = w;
        }
    }
}

// ---------------- k3: gate_up GEMM + SiLU*mul (tf32 mma, 4 warps, 3 CTA/SM) ----------------
template<bool ROUTED>
__global__ __launch_bounds__(128, 3) void k_gateup(const float* __restrict__ X,
                                                   const float* __restrict__ Wgu,
                                                   const float* __restrict__ Wsg,
                                                   const float* __restrict__ Wsu) {
    extern __shared__ float sm[];
    const int tid = threadIdx.x, n0 = blockIdx.x * 64;
    constexpr int LDC = ROUTED ? FI : FS;
    int M, m0;
    const float *bg, *bu; float* cout; const int* toks = nullptr;
    if (ROUTED) {
        const int e = blockIdx.y;
        m0 = blockIdx.z * 128;
        M = g_counts[e]; if (M > ECAP) M = ECAP;
        if (m0 >= M) return;
        const float* w = Wgu + (size_t)e * HID * (2 * FI);
        bg = w + n0; bu = w + FI + n0;
        cout = g_inter_r + (size_t)e * ECAP * FI;
        toks = g_slot_tok + e * ECAP;
    } else {
        m0 = blockIdx.y * 128; M = TOKS;
        bg = Wsg + n0; bu = Wsu + n0;
        cout = g_inter_s;
    }
    const uint32_t smb = (uint32_t)__cvta_generic_to_shared(sm);

    // A staging: 128x32 tile, 8 cp16/thread. Keep row indices + valid bitmask only.
    const int ac16 = tid & 7, arow0 = tid >> 3;
    int arow[8]; unsigned avm = 0;
#pragma unroll
    for (int i = 0; i < 8; i++) {
        int r = arow0 + 16 * i, m = m0 + r;
        bool v = m < M;
        arow[i] = ROUTED ? (v ? toks[m] : 0) : (v ? m : 0);
        if (v) avm |= (1u << i);
    }
    const uint32_t adst0 = smb + (uint32_t)(arow0 * A_STRIDE + ac16 * 4) * 4;
    const int bcol = (tid & 31) * 4, kr0 = tid >> 5;
    const float* bbase = ((bcol < 64) ? (bg + bcol) : (bu + bcol - 64)) + (size_t)kr0 * 3712;
    const uint32_t bdst0 = smb + (uint32_t)(B_BASEF + kr0 * B_STRIDE + bcol) * 4;

    auto load_tile = [&](int kt, int buf) {
        const float* Ak = X + kt * 32 + ac16 * 4;
#pragma unroll
        for (int i = 0; i < 8; i++)
            cp16(adst0 + (uint32_t)buf * (A_BUFSZ * 4) + (uint32_t)i * (16 * A_STRIDE * 4),
                 Ak + (size_t)arow[i] * HID, (avm >> i) & 1);
        const float* Bk = bbase + (size_t)kt * 32 * 3712;
#pragma unroll
        for (int i = 0; i < 8; i++)
            cp16(bdst0 + (uint32_t)buf * (B_BUFSZ * 4) + (uint32_t)i * (4 * B_STRIDE * 4),
                 Bk + (size_t)i * 4 * 3712, true);
    };

    const int lane = tid & 31, warp = tid >> 5;
    const int wm = warp >> 1, wn = warp & 1;
    const int gq = lane >> 2, tq = lane & 3;
    float acc[4][8][4];
#pragma unroll
    for (int mi = 0; mi < 4; mi++)
#pragma unroll
        for (int nj = 0; nj < 8; nj++)
#pragma unroll
            for (int q = 0; q < 4; q++) acc[mi][nj][q] = 0.f;

    auto compute_tile = [&](int buf) {
        const float* As = sm + buf * A_BUFSZ;
        const float* Bs = sm + B_BASEF + buf * B_BUFSZ;
#pragma unroll
        for (int ks = 0; ks < 4; ks++) {
            const int kk = ks * 8;
            uint32_t af[4][4];
#pragma unroll
            for (int mi = 0; mi < 4; mi++) {
                int r = wm * 64 + mi * 16 + gq;
                af[mi][0] = f2tf32(As[r * A_STRIDE + kk + tq]);
                af[mi][1] = f2tf32(As[(r + 8) * A_STRIDE + kk + tq]);
                af[mi][2] = f2tf32(As[r * A_STRIDE + kk + tq + 4]);
                af[mi][3] = f2tf32(As[(r + 8) * A_STRIDE + kk + tq + 4]);
            }
            uint32_t bf[8][2];
#pragma unroll
            for (int nj = 0; nj < 8; nj++) {
                int cB = wn * 64 + nj * 8 + gq;
                bf[nj][0] = f2tf32(Bs[(kk + tq) * B_STRIDE + cB]);
                bf[nj][1] = f2tf32(Bs[(kk + tq + 4) * B_STRIDE + cB]);
            }
#pragma unroll
            for (int mi = 0; mi < 4; mi++)
#pragma unroll
                for (int nj = 0; nj < 8; nj++)
                    mma_tf32(acc[mi][nj], af[mi], bf[nj][0], bf[nj][1]);
        }
    };

    load_tile(0, 0); cp_commit();
#pragma unroll 1
    for (int kt = 0; kt < 24; kt++) {
        int buf = kt & 1;
        if (kt + 1 < 24) { load_tile(kt + 1, buf ^ 1); cp_commit(); cp_wait<1>(); }
        else             { cp_wait<0>(); }
        __syncthreads();
        compute_tile(buf);
        __syncthreads();
    }

    // epilogue: gate warps (wn=0) park in smem; up warps (wn=1) fuse SiLU*up
    float* gex = sm;
    if (wn == 0) {
#pragma unroll
        for (int mi = 0; mi < 4; mi++) {
            int r = wm * 64 + mi * 16 + gq;
#pragma unroll
            for (int nj = 0; nj < 8; nj++) {
                int c = nj * 8 + tq * 2;
                gex[r * 68 + c] = acc[mi][nj][0];
                gex[r * 68 + c + 1] = acc[mi][nj][1];
                gex[(r + 8) * 68 + c] = acc[mi][nj][2];
                gex[(r + 8) * 68 + c + 1] = acc[mi][nj][3];
            }
        }
    }
    __syncthreads();
    if (wn == 1) {
#pragma unroll
        for (int mi = 0; mi < 4; mi++)
#pragma unroll
            for (int half = 0; half < 2; half++) {
                int rl = wm * 64 + mi * 16 + gq + half * 8;
                int m = m0 + rl;
                if (m < M) {
                    float* crow = cout + (size_t)m * LDC + n0;
#pragma unroll
                    for (int nj = 0; nj < 8; nj++) {
                        int c = nj * 8 + tq * 2;
                        float g0 = gex[rl * 68 + c], g1 = gex[rl * 68 + c + 1];
                        float u0 = half ? acc[mi][nj][2] : acc[mi][nj][0];
                        float u1 = half ? acc[mi][nj][3] : acc[mi][nj][1];
                        float2 o;
                        o.x = g0 / (1.f + expf(-g0)) * u0;
                        o.y = g1 / (1.f + expf(-g1)) * u1;
                        *reinterpret_cast<float2*>(crow + c) = o;
                    }
                }
            }
    }
}

// ---------------- k4: down-proj GEMM (tf32 mma, 4 warps, 3 CTA/SM) ----------------
template<bool ROUTED, int KDIM>
__global__ __launch_bounds__(128, 3) void k_down(const float* __restrict__ Bbase,
                                                 float* __restrict__ out) {
    extern __shared__ float sm[];
    const int tid = threadIdx.x, n0 = blockIdx.x * 128;
    int M, m0;
    const float *A, *Bd; const int* toks = nullptr; const float* wts = nullptr;
    if (ROUTED) {
        const int e = blockIdx.y;
        m0 = blockIdx.z * 128;
        M = g_counts[e]; if (M > ECAP) M = ECAP;
        if (m0 >= M) return;
        A = g_inter_r + (size_t)e * ECAP * FI;
        Bd = Bbase + (size_t)e * FI * HID;
        toks = g_slot_tok + e * ECAP;
        wts = g_slot_w + e * ECAP;
    } else {
        m0 = blockIdx.y * 128; M = TOKS;
        A = g_inter_s;
        Bd = Bbase;
    }
    const uint32_t smb = (uint32_t)__cvta_generic_to_shared(sm);

    const int ac16 = tid & 7, arow0 = tid >> 3;
    int arow[8]; unsigned avm = 0;
#pragma unroll
    for (int i = 0; i < 8; i++) {
        int r = arow0 + 16 * i, m = m0 + r;
        bool v = m < M;
        arow[i] = v ? m : 0;
        if (v) avm |= (1u << i);
    }
    const uint32_t adst0 = smb + (uint32_t)(arow0 * A_STRIDE + ac16 * 4) * 4;
    const int bcol = (tid & 31) * 4, kr0 = tid >> 5;
    const float* bbase = Bd + (size_t)kr0 * HID + n0 + bcol;
    const uint32_t bdst0 = smb + (uint32_t)(B_BASEF + kr0 * B_STRIDE + bcol) * 4;

    auto load_tile = [&](int kt, int buf) {
        const float* Ak = A + kt * 32 + ac16 * 4;
#pragma unroll
        for (int i = 0; i < 8; i++)
            cp16(adst0 + (uint32_t)buf * (A_BUFSZ * 4) + (uint32_t)i * (16 * A_STRIDE * 4),
                 Ak + (size_t)arow[i] * KDIM, (avm >> i) & 1);
        const float* Bk = bbase + (size_t)kt * 32 * HID;
#pragma unroll
        for (int i = 0; i < 8; i++)
            cp16(bdst0 + (uint32_t)buf * (B_BUFSZ * 4) + (uint32_t)i * (4 * B_STRIDE * 4),
                 Bk + (size_t)i * 4 * HID, true);
    };

    const int lane = tid & 31, warp = tid >> 5;
    const int wm = warp >> 1, wn = warp & 1;
    const int gq = lane >> 2, tq = lane & 3;
    float acc[4][8][4];
#pragma unroll
    for (int mi = 0; mi < 4; mi++)
#pragma unroll
        for (int nj = 0; nj < 8; nj++)
#pragma unroll
            for (int q = 0; q < 4; q++) acc[mi][nj][q] = 0.f;

    auto compute_tile = [&](int buf) {
        const float* As = sm + buf * A_BUFSZ;
        const float* Bs = sm + B_BASEF + buf * B_BUFSZ;
#pragma unroll
        for (int ks = 0; ks < 4; ks++) {
            const int kk = ks * 8;
            uint32_t af[4][4];
#pragma unroll
            for (int mi = 0; mi < 4; mi++) {
                int r = wm * 64 + mi * 16 + gq;
                af[mi][0] = f2tf32(As[r * A_STRIDE + kk + tq]);
                af[mi][1] = f2tf32(As[(r + 8) * A_STRIDE + kk + tq]);
                af[mi][2] = f2tf32(As[r * A_STRIDE + kk + tq + 4]);
                af[mi][3] = f2tf32(As[(r + 8) * A_STRIDE + kk + tq + 4]);
            }
            uint32_t bf[8][2];
#pragma unroll
            for (int nj = 0; nj < 8; nj++) {
                int cB = wn * 64 + nj * 8 + gq;
                bf[nj][0] = f2tf32(Bs[(kk + tq) * B_STRIDE + cB]);
                bf[nj][1] = f2tf32(Bs[(kk + tq + 4) * B_STRIDE + cB]);
            }
#pragma unroll
            for (int mi = 0; mi < 4; mi++)
#pragma unroll
                for (int nj = 0; nj < 8; nj++)
                    mma_tf32(acc[mi][nj], af[mi], bf[nj][0], bf[nj][1]);
        }
    };

    constexpr int KT = KDIM / 32;
    load_tile(0, 0); cp_commit();
#pragma unroll 1
    for (int kt = 0; kt < KT; kt++) {
        int buf = kt & 1;
        if (kt + 1 < KT) { load_tile(kt + 1, buf ^ 1); cp_commit(); cp_wait<1>(); }
        else             { cp_wait<0>(); }
        __syncthreads();
        compute_tile(buf);
        __syncthreads();
    }

#pragma unroll
    for (int mi = 0; mi < 4; mi++)
#pragma unroll
        for (int half = 0; half < 2; half++) {
            int r = m0 + wm * 64 + mi * 16 + gq + half * 8;
            if (r < M) {
                if (ROUTED) {
                    int tok = toks[r]; float w = wts[r];
                    float* orow = out + (size_t)tok * HID + n0 + wn * 64;
#pragma unroll
                    for (int nj = 0; nj < 8; nj++) {
                        int c = nj * 8 + tq * 2;
                        float v0 = (half ? acc[mi][nj][2] : acc[mi][nj][0]) * w;
                        float v1 = (half ? acc[mi][nj][3] : acc[mi][nj][1]) * w;
                        atomicAdd(orow + c, v0);
                        atomicAdd(orow + c + 1, v1);
                    }
                } else {
                    float* orow = out + (size_t)r * HID + n0 + wn * 64;
#pragma unroll
                    for (int nj = 0; nj < 8; nj++) {
                        int c = nj * 8 + tq * 2;
                        float2 o;
                        o.x = half ? acc[mi][nj][2] : acc[mi][nj][0];
                        o.y = half ? acc[mi][nj][3] : acc[mi][nj][1];
                        *reinterpret_cast<float2*>(orow + c) = o;
                    }
                }
            }
        }
}

// Force module (incl. 215MB of device globals) to load before harness checkpoints.
namespace {
struct ModuleWarmup {
    ModuleWarmup() {
        void* p = nullptr;
        cudaGetSymbolAddress(&p, g_inter_r);
        cudaGetSymbolAddress(&p, g_inter_s);
        cudaFuncSetAttribute(k_gateup<true>,  cudaFuncAttributeMaxDynamicSharedMemorySize, SMEM_BYTES);
        cudaFuncSetAttribute(k_gateup<false>, cudaFuncAttributeMaxDynamicSharedMemorySize, SMEM_BYTES);
        cudaFuncSetAttribute(k_down<true, FI>,  cudaFuncAttributeMaxDynamicSharedMemorySize, SMEM_BYTES);
        cudaFuncSetAttribute(k_down<false, FS>, cudaFuncAttributeMaxDynamicSharedMemorySize, SMEM_BYTES);
    }
};
ModuleWarmup g_warmup;
}

extern "C" void kernel_launch(void* const* d_in, const int* in_sizes, int n_in,
                              void* d_out, int out_size) {
    const float* X    = (const float*)d_in[0];
    const float* Wg   = (const float*)d_in[1];
    const float* ebia = (const float*)d_in[2];
    const float* Wgu  = (const float*)d_in[3];
    const float* Wdn  = (const float*)d_in[4];
    const float* Wsg  = (const float*)d_in[5];
    const float* Wsu  = (const float*)d_in[6];
    const float* Wsd  = (const float*)d_in[7];
    float* out = (float*)d_out;

    k_zero_counts<<<1, 128>>>();
    k_logits<<<TOKS / 64, 256>>>(X, Wg);
    k_topk<<<TOKS / 8, 256>>>(ebia);

    dim3 gs(FS / 64, TOKS / 128, 1);
    k_gateup<false><<<gs, 128, SMEM_BYTES>>>(X, nullptr, Wsg, Wsu);
    dim3 gr(FI / 64, NEXP, 2);
    k_gateup<true><<<gr, 128, SMEM_BYTES>>>(X, Wgu, nullptr, nullptr);

    dim3 ds(HID / 128, TOKS / 128, 1);
    k_down<false, FS><<<ds, 128, SMEM_BYTES>>>(Wsd, out);   // writes all of out
    dim3 dr(HID / 128, NEXP, 2);
    k_down<true, FI><<<dr, 128, SMEM_BYTES>>>(Wdn, out);    // atomicAdd on top
}

// round 12
// speedup vs baseline: 1.0032x; 1.0032x over previous
#include <cuda_runtime.h>
#include <cuda_bf16.h>
#include <cstdint>
#include <math.h>

#define TOKS 2048
#define HID  768
#define NEXP 128
#define FI   1856
#define FS   3712
#define NTOP 6
#define ECAP 192
#define RSCALE 2.5f

// ---------------- scratch (device globals; no allocation) ----------------
__device__ float g_logits[TOKS * NEXP];
__device__ int   g_counts[NEXP];
__device__ int   g_slot_tok[NEXP * ECAP];
__device__ float g_slot_w[NEXP * ECAP];
__device__ float g_inter_r[(size_t)NEXP * ECAP * FI];   // ~182 MB
__device__ float g_inter_s[(size_t)TOKS * FS];          // ~30 MB

// ---------------- smem geometry ----------------
#define A_STRIDE 36
#define B_STRIDE 136
#define A_BUFSZ  (128 * A_STRIDE)
#define B_BASEF  (2 * A_BUFSZ)
#define B_BUFSZ  (32 * B_STRIDE)
#define SMEM_BYTES ((2 * A_BUFSZ + 2 * B_BUFSZ) * 4)

// ---------------- PTX helpers ----------------
__device__ __forceinline__ uint32_t f2tf32(float f) {
    uint32_t u; asm("cvt.rna.tf32.f32 %0, %1;" : "=r"(u) : "f"(f)); return u;
}
__device__ __forceinline__ void mma_tf32(float* c, const uint32_t* a, uint32_t b0, uint32_t b1) {
    asm volatile("mma.sync.aligned.m16n8k8.row.col.f32.tf32.tf32.f32 "
        "{%0,%1,%2,%3},{%4,%5,%6,%7},{%8,%9},{%0,%1,%2,%3};"
        : "+f"(c[0]), "+f"(c[1]), "+f"(c[2]), "+f"(c[3])
        : "r"(a[0]), "r"(a[1]), "r"(a[2]), "r"(a[3]), "r"(b0), "r"(b1));
}
__device__ __forceinline__ void cp16(uint32_t dst, const float* src, bool valid) {
    int sz = valid ? 16 : 0;
    asm volatile("cp.async.cg.shared.global [%0], [%1], 16, %2;\n" :: "r"(dst), "l"(src), "r"(sz));
}
__device__ __forceinline__ void cp_commit() { asm volatile("cp.async.commit_group;\n"); }
template<int N> __device__ __forceinline__ void cp_wait() {
    asm volatile("cp.async.wait_group %0;\n" :: "n"(N));
}

// ---------------- k0: zero counters ----------------
__global__ void k_zero_counts() { if (threadIdx.x < NEXP) g_counts[threadIdx.x] = 0; }

// ---------------- k1: router logits (fp32, exact) ----------------
__global__ __launch_bounds__(256) void k_logits(const float* __restrict__ X,
                                                const float* __restrict__ Wg) {
    __shared__ float xs[64][16];
    __shared__ float ws[16][132];
    const int tid = threadIdx.x, t0 = blockIdx.x * 64;
    const int tt = tid >> 5, ee = tid & 31;
    float acc[8][4];
#pragma unroll
    for (int i = 0; i < 8; i++) { acc[i][0]=acc[i][1]=acc[i][2]=acc[i][3]=0.f; }
    for (int k0 = 0; k0 < HID; k0 += 16) {
#pragma unroll
        for (int i = 0; i < 4; i++) {
            int idx = tid + 256 * i;
            xs[idx >> 4][idx & 15] = X[(size_t)(t0 + (idx >> 4)) * HID + k0 + (idx & 15)];
        }
#pragma unroll
        for (int i = 0; i < 8; i++) {
            int idx = tid + 256 * i, e = idx >> 4, k = idx & 15;
            ws[k][e] = Wg[(size_t)e * HID + k0 + k];
        }
        __syncthreads();
#pragma unroll
        for (int k = 0; k < 16; k++) {
            float4 w4 = *reinterpret_cast<const float4*>(&ws[k][ee * 4]);
#pragma unroll
            for (int i = 0; i < 8; i++) {
                float xv = xs[tt * 8 + i][k];
                acc[i][0] += xv * w4.x; acc[i][1] += xv * w4.y;
                acc[i][2] += xv * w4.z; acc[i][3] += xv * w4.w;
            }
        }
        __syncthreads();
    }
#pragma unroll
    for (int i = 0; i < 8; i++)
#pragma unroll
        for (int j = 0; j < 4; j++)
            g_logits[(size_t)(t0 + tt * 8 + i) * NEXP + ee * 4 + j] = acc[i][j];
}

// ---------------- k2: top-6 + capacity dispatch (warp per token) ----------------
__global__ __launch_bounds__(256) void k_topk(const float* __restrict__ e_bias) {
    const int warp = threadIdx.x >> 5, lane = threadIdx.x & 31;
    const int t = blockIdx.x * 8 + warp;
    float4 lg4 = *reinterpret_cast<const float4*>(&g_logits[(size_t)t * NEXP + lane * 4]);
    float4 b4  = *reinterpret_cast<const float4*>(&e_bias[lane * 4]);
    float sig[4], ch[4];
    sig[0] = 1.f / (1.f + expf(-lg4.x)); ch[0] = sig[0] + b4.x;
    sig[1] = 1.f / (1.f + expf(-lg4.y)); ch[1] = sig[1] + b4.y;
    sig[2] = 1.f / (1.f + expf(-lg4.z)); ch[2] = sig[2] + b4.z;
    sig[3] = 1.f / (1.f + expf(-lg4.w)); ch[3] = sig[3] + b4.w;

    int my_ex = 0; float my_sig = 0.f;
    float wsum = 0.f;
#pragma unroll
    for (int r = 0; r < NTOP; r++) {
        float bv = ch[0]; int bi = lane * 4;
        if (ch[1] > bv) { bv = ch[1]; bi = lane * 4 + 1; }
        if (ch[2] > bv) { bv = ch[2]; bi = lane * 4 + 2; }
        if (ch[3] > bv) { bv = ch[3]; bi = lane * 4 + 3; }
#pragma unroll
        for (int s = 16; s > 0; s >>= 1) {
            float ov = __shfl_xor_sync(0xffffffffu, bv, s);
            int   oi = __shfl_xor_sync(0xffffffffu, bi, s);
            if (ov > bv || (ov == bv && oi < bi)) { bv = ov; bi = oi; }
        }
        int j = bi & 3;
        float sj = (j == 0) ? sig[0] : (j == 1) ? sig[1] : (j == 2) ? sig[2] : sig[3];
        float ws = __shfl_sync(0xffffffffu, sj, bi >> 2);
        wsum += ws;
        if (lane == r) { my_ex = bi; my_sig = ws; }
        if (lane == (bi >> 2)) {
            if (j == 0) ch[0] = -1e30f; else if (j == 1) ch[1] = -1e30f;
            else if (j == 2) ch[2] = -1e30f; else ch[3] = -1e30f;
        }
    }
    if (lane < NTOP) {
        float w = my_sig / (wsum + 1e-20f) * RSCALE;
        int pos = atomicAdd(&g_counts[my_ex], 1);
        if (pos < ECAP) {
            g_slot_tok[my_ex * ECAP + pos] = t;
            g_slot_w[my_ex * ECAP + pos] = w;
        }
    }
}

// ---------------- k3: gate_up GEMM + SiLU*mul (tf32 mma, 4 warps, 3 CTA/SM) ----------------
template<bool ROUTED>
__global__ __launch_bounds__(128, 3) void k_gateup(const float* __restrict__ X,
                                                   const float* __restrict__ Wgu,
                                                   const float* __restrict__ Wsg,
                                                   const float* __restrict__ Wsu) {
    extern __shared__ float sm[];
    const int tid = threadIdx.x, n0 = blockIdx.x * 64;
    constexpr int LDC = ROUTED ? FI : FS;
    int M, m0;
    const float *bg, *bu; float* cout; const int* toks = nullptr;
    if (ROUTED) {
        const int e = blockIdx.y;
        m0 = blockIdx.z * 128;
        M = g_counts[e]; if (M > ECAP) M = ECAP;
        if (m0 >= M) return;
        const float* w = Wgu + (size_t)e * HID * (2 * FI);
        bg = w + n0; bu = w + FI + n0;
        cout = g_inter_r + (size_t)e * ECAP * FI;
        toks = g_slot_tok + e * ECAP;
    } else {
        m0 = blockIdx.y * 128; M = TOKS;
        bg = Wsg + n0; bu = Wsu + n0;
        cout = g_inter_s;
    }
    const uint32_t smb = (uint32_t)__cvta_generic_to_shared(sm);

    // A staging: 128x32 tile, 8 cp16/thread. Keep row indices + valid bitmask only.
    const int ac16 = tid & 7, arow0 = tid >> 3;
    int arow[8]; unsigned avm = 0;
#pragma unroll
    for (int i = 0; i < 8; i++) {
        int r = arow0 + 16 * i, m = m0 + r;
        bool v = m < M;
        arow[i] = ROUTED ? (v ? toks[m] : 0) : (v ? m : 0);
        if (v) avm |= (1u << i);
    }
    const uint32_t adst0 = smb + (uint32_t)(arow0 * A_STRIDE + ac16 * 4) * 4;
    const int bcol = (tid & 31) * 4, kr0 = tid >> 5;
    const float* bbase = ((bcol < 64) ? (bg + bcol) : (bu + bcol - 64)) + (size_t)kr0 * 3712;
    const uint32_t bdst0 = smb + (uint32_t)(B_BASEF + kr0 * B_STRIDE + bcol) * 4;

    auto load_tile = [&](int kt, int buf) {
        const float* Ak = X + kt * 32 + ac16 * 4;
#pragma unroll
        for (int i = 0; i < 8; i++)
            cp16(adst0 + (uint32_t)buf * (A_BUFSZ * 4) + (uint32_t)i * (16 * A_STRIDE * 4),
                 Ak + (size_t)arow[i] * HID, (avm >> i) & 1);
        const float* Bk = bbase + (size_t)kt * 32 * 3712;
#pragma unroll
        for (int i = 0; i < 8; i++)
            cp16(bdst0 + (uint32_t)buf * (B_BUFSZ * 4) + (uint32_t)i * (4 * B_STRIDE * 4),
                 Bk + (size_t)i * 4 * 3712, true);
    };

    const int lane = tid & 31, warp = tid >> 5;
    const int wm = warp >> 1, wn = warp & 1;
    const int gq = lane >> 2, tq = lane & 3;
    float acc[4][8][4];
#pragma unroll
    for (int mi = 0; mi < 4; mi++)
#pragma unroll
        for (int nj = 0; nj < 8; nj++)
#pragma unroll
            for (int q = 0; q < 4; q++) acc[mi][nj][q] = 0.f;

    auto compute_tile = [&](int buf) {
        const float* As = sm + buf * A_BUFSZ;
        const float* Bs = sm + B_BASEF + buf * B_BUFSZ;
#pragma unroll
        for (int ks = 0; ks < 4; ks++) {
            const int kk = ks * 8;
            uint32_t af[4][4];
#pragma unroll
            for (int mi = 0; mi < 4; mi++) {
                int r = wm * 64 + mi * 16 + gq;
                af[mi][0] = f2tf32(As[r * A_STRIDE + kk + tq]);
                af[mi][1] = f2tf32(As[(r + 8) * A_STRIDE + kk + tq]);
                af[mi][2] = f2tf32(As[r * A_STRIDE + kk + tq + 4]);
                af[mi][3] = f2tf32(As[(r + 8) * A_STRIDE + kk + tq + 4]);
            }
            uint32_t bf[8][2];
#pragma unroll
            for (int nj = 0; nj < 8; nj++) {
                int cB = wn * 64 + nj * 8 + gq;
                bf[nj][0] = f2tf32(Bs[(kk + tq) * B_STRIDE + cB]);
                bf[nj][1] = f2tf32(Bs[(kk + tq + 4) * B_STRIDE + cB]);
            }
#pragma unroll
            for (int mi = 0; mi < 4; mi++)
#pragma unroll
                for (int nj = 0; nj < 8; nj++)
                    mma_tf32(acc[mi][nj], af[mi], bf[nj][0], bf[nj][1]);
        }
    };

    load_tile(0, 0); cp_commit();
#pragma unroll 1
    for (int kt = 0; kt < 24; kt++) {
        int buf = kt & 1;
        if (kt + 1 < 24) { load_tile(kt + 1, buf ^ 1); cp_commit(); cp_wait<1>(); }
        else             { cp_wait<0>(); }
        __syncthreads();
        compute_tile(buf);
        __syncthreads();
    }

    // epilogue: gate warps (wn=0) park in smem; up warps (wn=1) fuse SiLU*up
    float* gex = sm;
    if (wn == 0) {
#pragma unroll
        for (int mi = 0; mi < 4; mi++) {
            int r = wm * 64 + mi * 16 + gq;
#pragma unroll
            for (int nj = 0; nj < 8; nj++) {
                int c = nj * 8 + tq * 2;
                gex[r * 68 + c] = acc[mi][nj][0];
                gex[r * 68 + c + 1] = acc[mi][nj][1];
                gex[(r + 8) * 68 + c] = acc[mi][nj][2];
                gex[(r + 8) * 68 + c + 1] = acc[mi][nj][3];
            }
        }
    }
    __syncthreads();
    if (wn == 1) {
#pragma unroll
        for (int mi = 0; mi < 4; mi++)
#pragma unroll
            for (int half = 0; half < 2; half++) {
                int rl = wm * 64 + mi * 16 + gq + half * 8;
                int m = m0 + rl;
                if (m < M) {
                    float* crow = cout + (size_t)m * LDC + n0;
#pragma unroll
                    for (int nj = 0; nj < 8; nj++) {
                        int c = nj * 8 + tq * 2;
                        float g0 = gex[rl * 68 + c], g1 = gex[rl * 68 + c + 1];
                        float u0 = half ? acc[mi][nj][2] : acc[mi][nj][0];
                        float u1 = half ? acc[mi][nj][3] : acc[mi][nj][1];
                        float2 o;
                        o.x = g0 / (1.f + expf(-g0)) * u0;
                        o.y = g1 / (1.f + expf(-g1)) * u1;
                        *reinterpret_cast<float2*>(crow + c) = o;
                    }
                }
            }
    }
}

// ---------------- k4: down-proj GEMM (tf32 mma, 4 warps, 3 CTA/SM) ----------------
template<bool ROUTED, int KDIM>
__global__ __launch_bounds__(128, 3) void k_down(const float* __restrict__ Bbase,
                                                 float* __restrict__ out) {
    extern __shared__ float sm[];
    const int tid = threadIdx.x, n0 = blockIdx.x * 128;
    int M, m0;
    const float *A, *Bd; const int* toks = nullptr; const float* wts = nullptr;
    if (ROUTED) {
        const int e = blockIdx.y;
        m0 = blockIdx.z * 128;
        M = g_counts[e]; if (M > ECAP) M = ECAP;
        if (m0 >= M) return;
        A = g_inter_r + (size_t)e * ECAP * FI;
        Bd = Bbase + (size_t)e * FI * HID;
        toks = g_slot_tok + e * ECAP;
        wts = g_slot_w + e * ECAP;
    } else {
        m0 = blockIdx.y * 128; M = TOKS;
        A = g_inter_s;
        Bd = Bbase;
    }
    const uint32_t smb = (uint32_t)__cvta_generic_to_shared(sm);

    const int ac16 = tid & 7, arow0 = tid >> 3;
    int arow[8]; unsigned avm = 0;
#pragma unroll
    for (int i = 0; i < 8; i++) {
        int r = arow0 + 16 * i, m = m0 + r;
        bool v = m < M;
        arow[i] = v ? m : 0;
        if (v) avm |= (1u << i);
    }
    const uint32_t adst0 = smb + (uint32_t)(arow0 * A_STRIDE + ac16 * 4) * 4;
    const int bcol = (tid & 31) * 4, kr0 = tid >> 5;
    const float* bbase = Bd + (size_t)kr0 * HID + n0 + bcol;
    const uint32_t bdst0 = smb + (uint32_t)(B_BASEF + kr0 * B_STRIDE + bcol) * 4;

    auto load_tile = [&](int kt, int buf) {
        const float* Ak = A + kt * 32 + ac16 * 4;
#pragma unroll
        for (int i = 0; i < 8; i++)
            cp16(adst0 + (uint32_t)buf * (A_BUFSZ * 4) + (uint32_t)i * (16 * A_STRIDE * 4),
                 Ak + (size_t)arow[i] * KDIM, (avm >> i) & 1);
        const float* Bk = bbase + (size_t)kt * 32 * HID;
#pragma unroll
        for (int i = 0; i < 8; i++)
            cp16(bdst0 + (uint32_t)buf * (B_BUFSZ * 4) + (uint32_t)i * (4 * B_STRIDE * 4),
                 Bk + (size_t)i * 4 * HID, true);
    };

    const int lane = tid & 31, warp = tid >> 5;
    const int wm = warp >> 1, wn = warp & 1;
    const int gq = lane >> 2, tq = lane & 3;
    float acc[4][8][4];
#pragma unroll
    for (int mi = 0; mi < 4; mi++)
#pragma unroll
        for (int nj = 0; nj < 8; nj++)
#pragma unroll
            for (int q = 0; q < 4; q++) acc[mi][nj][q] = 0.f;

    auto compute_tile = [&](int buf) {
        const float* As = sm + buf * A_BUFSZ;
        const float* Bs = sm + B_BASEF + buf * B_BUFSZ;
#pragma unroll
        for (int ks = 0; ks < 4; ks++) {
            const int kk = ks * 8;
            uint32_t af[4][4];
#pragma unroll
            for (int mi = 0; mi < 4; mi++) {
                int r = wm * 64 + mi * 16 + gq;
                af[mi][0] = f2tf32(As[r * A_STRIDE + kk + tq]);
                af[mi][1] = f2tf32(As[(r + 8) * A_STRIDE + kk + tq]);
                af[mi][2] = f2tf32(As[r * A_STRIDE + kk + tq + 4]);
                af[mi][3] = f2tf32(As[(r + 8) * A_STRIDE + kk + tq + 4]);
            }
            uint32_t bf[8][2];
#pragma unroll
            for (int nj = 0; nj < 8; nj++) {
                int cB = wn * 64 + nj * 8 + gq;
                bf[nj][0] = f2tf32(Bs[(kk + tq) * B_STRIDE + cB]);
                bf[nj][1] = f2tf32(Bs[(kk + tq + 4) * B_STRIDE + cB]);
            }
#pragma unroll
            for (int mi = 0; mi < 4; mi++)
#pragma unroll
                for (int nj = 0; nj < 8; nj++)
                    mma_tf32(acc[mi][nj], af[mi], bf[nj][0], bf[nj][1]);
        }
    };

    constexpr int KT = KDIM / 32;
    load_tile(0, 0); cp_commit();
#pragma unroll 1
    for (int kt = 0; kt < KT; kt++) {
        int buf = kt & 1;
        if (kt + 1 < KT) { load_tile(kt + 1, buf ^ 1); cp_commit(); cp_wait<1>(); }
        else             { cp_wait<0>(); }
        __syncthreads();
        compute_tile(buf);
        __syncthreads();
    }

#pragma unroll
    for (int mi = 0; mi < 4; mi++)
#pragma unroll
        for (int half = 0; half < 2; half++) {
            int r = m0 + wm * 64 + mi * 16 + gq + half * 8;
            if (r < M) {
                if (ROUTED) {
                    int tok = toks[r]; float w = wts[r];
                    float* orow = out + (size_t)tok * HID + n0 + wn * 64;
#pragma unroll
                    for (int nj = 0; nj < 8; nj++) {
                        int c = nj * 8 + tq * 2;
                        float v0 = (half ? acc[mi][nj][2] : acc[mi][nj][0]) * w;
                        float v1 = (half ? acc[mi][nj][3] : acc[mi][nj][1]) * w;
                        atomicAdd(orow + c, v0);
                        atomicAdd(orow + c + 1, v1);
                    }
                } else {
                    float* orow = out + (size_t)r * HID + n0 + wn * 64;
#pragma unroll
                    for (int nj = 0; nj < 8; nj++) {
                        int c = nj * 8 + tq * 2;
                        float2 o;
                        o.x = half ? acc[mi][nj][2] : acc[mi][nj][0];
                        o.y = half ? acc[mi][nj][3] : acc[mi][nj][1];
                        *reinterpret_cast<float2*>(orow + c) = o;
                    }
                }
            }
        }
}

// Force module (incl. 215MB of device globals) to load before harness checkpoints.
namespace {
struct ModuleWarmup {
    ModuleWarmup() {
        void* p = nullptr;
        cudaGetSymbolAddress(&p, g_inter_r);
        cudaGetSymbolAddress(&p, g_inter_s);
        cudaFuncSetAttribute(k_gateup<true>,  cudaFuncAttributeMaxDynamicSharedMemorySize, SMEM_BYTES);
        cudaFuncSetAttribute(k_gateup<false>, cudaFuncAttributeMaxDynamicSharedMemorySize, SMEM_BYTES);
        cudaFuncSetAttribute(k_down<true, FI>,  cudaFuncAttributeMaxDynamicSharedMemorySize, SMEM_BYTES);
        cudaFuncSetAttribute(k_down<false, FS>, cudaFuncAttributeMaxDynamicSharedMemorySize, SMEM_BYTES);
    }
};
ModuleWarmup g_warmup;
}

extern "C" void kernel_launch(void* const* d_in, const int* in_sizes, int n_in,
                              void* d_out, int out_size) {
    const float* X    = (const float*)d_in[0];
    const float* Wg   = (const float*)d_in[1];
    const float* ebia = (const float*)d_in[2];
    const float* Wgu  = (const float*)d_in[3];
    const float* Wdn  = (const float*)d_in[4];
    const float* Wsg  = (const float*)d_in[5];
    const float* Wsu  = (const float*)d_in[6];
    const float* Wsd  = (const float*)d_in[7];
    float* out = (float*)d_out;

    k_zero_counts<<<1, 128>>>();
    k_logits<<<TOKS / 64, 256>>>(X, Wg);
    k_topk<<<TOKS / 8, 256>>>(ebia);

    dim3 gs(FS / 64, TOKS / 128, 1);
    k_gateup<false><<<gs, 128, SMEM_BYTES>>>(X, nullptr, Wsg, Wsu);
    dim3 gr(FI / 64, NEXP, 2);
    k_gateup<true><<<gr, 128, SMEM_BYTES>>>(X, Wgu, nullptr, nullptr);

    dim3 ds(HID / 128, TOKS / 128, 1);
    k_down<false, FS><<<ds, 128, SMEM_BYTES>>>(Wsd, out);   // writes all of out
    dim3 dr(HID / 128, NEXP, 2);
    k_down<true, FI><<<dr, 128, SMEM_BYTES>>>(Wdn, out);    // atomicAdd on top
}